// round 7
// baseline (speedup 1.0000x reference)
#include <cuda_runtime.h>
#include <cuda_bf16.h>

typedef unsigned long long u64;

#define NMAX 100000

// ---------------- device scratch (no allocations allowed) ----------------
__device__ float g_agg[NMAX];
__device__ int   g_deg[NMAX];
__device__ float g_tmp[NMAX];
__device__ int   g_degmax;
__device__ float g_sum_agg;
__device__ float g_sum_score;
__device__ float g_sumsq;

// ---------------- packed weight image (u64 = {w[j][2i], w[j][2i+1]}) -----
// K-dimension pair packing. Row bases even (16B aligned). u64 units:
#define OFF_SW 0        // 35 rows x 5 kpairs, stride 6
#define OFF_SB 210      // 35 x {b,0} + pad
#define OFF_HW 246      // 3 x (35 rows x 18 kpairs, stride 18)
#define OFF_HB 2136     // 3 x 36 x {b,0}
#define OFF_EW 2244     // 5 rows x 18 kpairs
#define OFF_EB 2334     // 5 x {b,0} + pad
#define NET_STRIDE 2340
#define WPACK_U64 (2 * NET_STRIDE)   // 4680 u64 = 37440 B

__device__ u64 g_wpack[WPACK_U64];

// R-net weights in constant memory (ulonglong2 units = 2 kpairs each).
// u2 offsets: SW 0 (stride 3), SB 105, HW m: 123+m*315, HB m: 1068+m*18,
//             EW 1122 (stride 9), EB 1167.  Total 1170 u2 = 18720 B.
#define CW_U2 (NET_STRIDE / 2)
__constant__ ulonglong2 c_w[CW_U2];

// ---------------- packed f32x2 helpers ----------------
__device__ __forceinline__ u64 fma2(u64 a, u64 b, u64 c) {
    u64 d;
    asm("fma.rn.f32x2 %0, %1, %2, %3;" : "=l"(d) : "l"(a), "l"(b), "l"(c));
    return d;
}
__device__ __forceinline__ u64 add2(u64 a, u64 b) {
    u64 d;
    asm("add.rn.f32x2 %0, %1, %2;" : "=l"(d) : "l"(a), "l"(b));
    return d;
}
__device__ __forceinline__ u64 pk(float lo, float hi) {
    return ((u64)__float_as_uint(hi) << 32) | (u64)__float_as_uint(lo);
}
__device__ __forceinline__ float lo32(u64 a) { return __uint_as_float((unsigned)a); }
__device__ __forceinline__ float hi32(u64 a) { return __uint_as_float((unsigned)(a >> 32)); }
__device__ __forceinline__ float sigmoidf(float v) {
    return 1.0f / (1.0f + __expf(-v));
}
__device__ __forceinline__ float hsum(u64 a0, u64 a1) {
    u64 s = add2(a0, a1);
    return lo32(s) + hi32(s);
}

// ---------------- smem-weight rowdot / layer (P net) ----------------
template<int KPAIR>
__device__ __forceinline__ float rowdot(const u64* __restrict__ wr, u64 binit,
                                        const u64* __restrict__ xin) {
    u64 a0 = binit, a1 = 0ull;
#pragma unroll
    for (int i = 0; i + 1 < KPAIR; i += 2) {
        ulonglong2 w2 = *reinterpret_cast<const ulonglong2*>(wr + i);
        a0 = fma2(w2.x, xin[i],     a0);
        a1 = fma2(w2.y, xin[i + 1], a1);
    }
    if (KPAIR & 1) a0 = fma2(wr[KPAIR - 1], xin[KPAIR - 1], a0);
    return hsum(a0, a1);
}

template<int NOUT, int KPAIR, int STRIDE, bool RELU>
__device__ __forceinline__ void layer(const u64* __restrict__ w,
                                      const u64* __restrict__ b,
                                      const u64* __restrict__ xin,
                                      u64* __restrict__ xout) {
#pragma unroll
    for (int jp = 0; jp < NOUT / 2; jp++) {
        float v0 = rowdot<KPAIR>(w + (2 * jp)     * STRIDE, b[2 * jp],     xin);
        float v1 = rowdot<KPAIR>(w + (2 * jp + 1) * STRIDE, b[2 * jp + 1], xin);
        if (RELU) { v0 = fmaxf(v0, 0.0f); v1 = fmaxf(v1, 0.0f); }
        xout[jp] = pk(v0, v1);
    }
    if (NOUT & 1) {
        float v = rowdot<KPAIR>(w + (NOUT - 1) * STRIDE, b[NOUT - 1], xin);
        if (RELU) v = fmaxf(v, 0.0f);
        xout[NOUT / 2] = pk(v, 0.0f);
    }
}

// ---------------- const-weight rowdot / layer (R net) ----------------
// Direct c_w[index] array accesses with compile-time indices so the compiler
// keeps them on the constant port (LDC/LDCU), off the L1tex crossbar.
template<int KPAIR>
__device__ __forceinline__ float rowdot_c(int baseU2, u64 binit,
                                          const u64* __restrict__ xin) {
    u64 a0 = binit, a1 = 0ull;
#pragma unroll
    for (int i = 0; i + 1 < KPAIR; i += 2) {
        ulonglong2 w2 = c_w[baseU2 + (i >> 1)];
        a0 = fma2(w2.x, xin[i],     a0);
        a1 = fma2(w2.y, xin[i + 1], a1);
    }
    if (KPAIR & 1) {
        ulonglong2 w2 = c_w[baseU2 + (KPAIR >> 1)];
        a0 = fma2(w2.x, xin[KPAIR - 1], a0);
    }
    return hsum(a0, a1);
}

template<int NOUT, int KPAIR, int STRIDE_U2, bool RELU>
__device__ __forceinline__ void layer_c(int wU2, int bU2,
                                        const u64* __restrict__ xin,
                                        u64* __restrict__ xout) {
#pragma unroll
    for (int jp = 0; jp < NOUT / 2; jp++) {
        ulonglong2 b2 = c_w[bU2 + jp];   // {b_2jp,0}, {b_2jp+1,0}
        float v0 = rowdot_c<KPAIR>(wU2 + (2 * jp)     * STRIDE_U2, b2.x, xin);
        float v1 = rowdot_c<KPAIR>(wU2 + (2 * jp + 1) * STRIDE_U2, b2.y, xin);
        if (RELU) { v0 = fmaxf(v0, 0.0f); v1 = fmaxf(v1, 0.0f); }
        xout[jp] = pk(v0, v1);
    }
    if (NOUT & 1) {
        ulonglong2 b2 = c_w[bU2 + NOUT / 2];
        float v = rowdot_c<KPAIR>(wU2 + (NOUT - 1) * STRIDE_U2, b2.x, xin);
        if (RELU) v = fmaxf(v, 0.0f);
        xout[NOUT / 2] = pk(v, 0.0f);
    }
}

// ---------------- kernels ----------------
__global__ void zero_kernel(int N) {
    int i = blockIdx.x * blockDim.x + threadIdx.x;
    if (i < N) { g_agg[i] = 0.0f; g_deg[i] = 0; }
}

__global__ void scal_kernel() {
    g_degmax = 0; g_sum_agg = 0.0f; g_sum_score = 0.0f; g_sumsq = 0.0f;
}

// Single block: build the K-pair-packed weight image once.
__global__ void prep_kernel(
    const float* __restrict__ Rsw, const float* __restrict__ Rsb,
    const float* __restrict__ Rhw, const float* __restrict__ Rhb,
    const float* __restrict__ Rew, const float* __restrict__ Reb,
    const float* __restrict__ Psw, const float* __restrict__ Psb,
    const float* __restrict__ Phw, const float* __restrict__ Phb,
    const float* __restrict__ Pew, const float* __restrict__ Peb)
{
    const int t = threadIdx.x, nt = blockDim.x;
    float* wf = reinterpret_cast<float*>(g_wpack);
    for (int k = t; k < 2 * WPACK_U64; k += nt) wf[k] = 0.0f;
    __syncthreads();

    auto putm = [&](const float* __restrict__ s, int offU, int rows, int cols, int stride) {
        int n = rows * cols;
        for (int k = t; k < n; k += nt) {
            int j = k / cols, i = k - j * cols;
            wf[(offU + j * stride + (i >> 1)) * 2 + (i & 1)] = s[k];
        }
    };
    auto putb = [&](const float* __restrict__ s, int offU, int n) {
        for (int j = t; j < n; j += nt)
            wf[(offU + j) * 2] = s[j];              // {b, 0}
    };

    // R net (copied to constant memory afterwards)
    putm(Rsw, OFF_SW, 35, 10, 6);
    putb(Rsb, OFF_SB, 35);
    for (int m = 0; m < 3; m++) {
        putm(Rhw + m * 35 * 35, OFF_HW + m * 630, 35, 35, 18);
        putb(Rhb + m * 35,      OFF_HB + m * 36, 35);
    }
    putm(Rew, OFF_EW, 5, 35, 18);   // only first 5 output rows needed
    putb(Reb, OFF_EB, 5);
    // P net (stays in smem)
    putm(Psw, NET_STRIDE + OFF_SW, 35, 10, 6);
    putb(Psb, NET_STRIDE + OFF_SB, 35);
    for (int m = 0; m < 3; m++) {
        putm(Phw + m * 35 * 35, NET_STRIDE + OFF_HW + m * 630, 35, 35, 18);
        putb(Phb + m * 35,      NET_STRIDE + OFF_HB + m * 36, 35);
    }
    putm(Pew, NET_STRIDE + OFF_EW, 5, 35, 18);
    putb(Peb, NET_STRIDE + OFF_EB, 5);
}

// No min-blocks bound: spills cost more than occupancy here.
__global__ void __launch_bounds__(128) edge_kernel(
    const float* __restrict__ score,
    const int*   __restrict__ edge_idx,
    const float* __restrict__ outcome,
    int E)
{
    __shared__ __align__(16) u64 wsm[NET_STRIDE];   // P net only (18.7 KB)
    const int t = threadIdx.x, nt = blockDim.x;

    {
        const ulonglong2* src = reinterpret_cast<const ulonglong2*>(g_wpack + NET_STRIDE);
        ulonglong2* dst = reinterpret_cast<ulonglong2*>(wsm);
        for (int k = t; k < NET_STRIDE / 2; k += nt) dst[k] = src[k];
    }
    __syncthreads();

    const int e = blockIdx.x * blockDim.x + t;
    if (e >= E) return;

    int idx[10];
    {
        const int2* ei2 = reinterpret_cast<const int2*>(edge_idx + (size_t)e * 10);
#pragma unroll
        for (int k = 0; k < 5; k++) {
            int2 q = ei2[k];
            idx[2 * k] = q.x; idx[2 * k + 1] = q.y;
        }
    }
    float xsc[10];
#pragma unroll
    for (int i = 0; i < 10; i++) xsc[i] = score[idx[i]];

    const bool o = outcome[e] > 0.0f;

    // ---------------- R net: const weights, orientation fwd = o ----------
    {
        const bool fwd = o;
        u64 xa[18], xb[18];
#pragma unroll
        for (int i = 0; i < 5; i++)
            xa[i] = fwd ? pk(xsc[2 * i], xsc[2 * i + 1])
                        : pk(xsc[9 - 2 * i], xsc[8 - 2 * i]);

        layer_c<35,  5, 3, true >(0,            105, xa, xb);
        layer_c<35, 18, 9, true >(123,          1068, xb, xa);
        layer_c<35, 18, 9, true >(123 + 315,    1068 + 18, xa, xb);
        layer_c<35, 18, 9, true >(123 + 630,    1068 + 36, xb, xa);
        u64 eo[3];
        layer_c< 5, 18, 9, false>(1122,         1167, xa, eo);

        const int base = o ? 0 : 5;
        atomicAdd(&g_agg[idx[base + 0]],  sigmoidf(lo32(eo[0])));
        atomicAdd(&g_agg[idx[base + 1]],  sigmoidf(hi32(eo[0])));
        atomicAdd(&g_agg[idx[base + 2]],  sigmoidf(lo32(eo[1])));
        atomicAdd(&g_agg[idx[base + 3]],  sigmoidf(hi32(eo[1])));
        atomicAdd(&g_agg[idx[base + 4]],  sigmoidf(lo32(eo[2])));
    }

    // ---------------- P net: smem weights, orientation fwd = !o ----------
    {
        const bool fwd = !o;
        u64 xa[18], xb[18];
#pragma unroll
        for (int i = 0; i < 5; i++)
            xa[i] = fwd ? pk(xsc[2 * i], xsc[2 * i + 1])
                        : pk(xsc[9 - 2 * i], xsc[8 - 2 * i]);

        layer<35,  5,  6, true >(wsm + OFF_SW,        wsm + OFF_SB,      xa, xb);
        layer<35, 18, 18, true >(wsm + OFF_HW,        wsm + OFF_HB,      xb, xa);
        layer<35, 18, 18, true >(wsm + OFF_HW +  630, wsm + OFF_HB + 36, xa, xb);
        layer<35, 18, 18, true >(wsm + OFF_HW + 1260, wsm + OFF_HB + 72, xb, xa);
        u64 eo[3];
        layer< 5, 18, 18, false>(wsm + OFF_EW,        wsm + OFF_EB,      xa, eo);

        const int base = o ? 5 : 0;
        atomicAdd(&g_agg[idx[base + 0]], -sigmoidf(lo32(eo[0])));
        atomicAdd(&g_agg[idx[base + 1]], -sigmoidf(hi32(eo[0])));
        atomicAdd(&g_agg[idx[base + 2]], -sigmoidf(lo32(eo[1])));
        atomicAdd(&g_agg[idx[base + 3]], -sigmoidf(hi32(eo[1])));
        atomicAdd(&g_agg[idx[base + 4]], -sigmoidf(lo32(eo[2])));
    }

#pragma unroll
    for (int k = 0; k < 10; k++) atomicAdd(&g_deg[idx[k]], 1);
}

__device__ __forceinline__ float warp_sum(float v) {
#pragma unroll
    for (int s = 16; s; s >>= 1) v += __shfl_xor_sync(0xffffffffu, v, s);
    return v;
}
__device__ __forceinline__ int warp_max(int v) {
#pragma unroll
    for (int s = 16; s; s >>= 1) v = max(v, __shfl_xor_sync(0xffffffffu, v, s));
    return v;
}

__global__ void reduce1_kernel(const float* __restrict__ score, int N) {
    int i = blockIdx.x * blockDim.x + threadIdx.x;
    int d = 0; float sa = 0.0f, ss = 0.0f;
    if (i < N) { d = g_deg[i]; sa = g_agg[i]; ss = score[i]; }
    sa = warp_sum(sa); ss = warp_sum(ss); d = warp_max(d);
    if ((threadIdx.x & 31) == 0) {
        atomicMax(&g_degmax, d);
        atomicAdd(&g_sum_agg, sa);
        atomicAdd(&g_sum_score, ss);
    }
}

__global__ void reduce2_kernel(const float* __restrict__ score, int N) {
    const float c    = 2.0f / (float)g_degmax;          // NORM_FACTOR / deg.max()
    const float mean = (g_sum_score + c * g_sum_agg) / (float)N;
    int i = blockIdx.x * blockDim.x + threadIdx.x;
    float u = 0.0f;
    if (i < N) { u = score[i] + c * g_agg[i] - mean; g_tmp[i] = u; }
    float sq = warp_sum(u * u);
    if ((threadIdx.x & 31) == 0) atomicAdd(&g_sumsq, sq);
}

__global__ void finalize_kernel(float* __restrict__ out, int N) {
    int i = blockIdx.x * blockDim.x + threadIdx.x;
    if (i < N) out[i] = g_tmp[i] * rsqrtf(g_sumsq);
}

// ---------------- launch ----------------
extern "C" void kernel_launch(void* const* d_in, const int* in_sizes, int n_in,
                              void* d_out, int out_size) {
    const float* score    = (const float*)d_in[0];
    const int*   edge_idx = (const int*)  d_in[1];
    const float* outcome  = (const float*)d_in[2];
    const float* Rsw = (const float*)d_in[3],  *Rsb = (const float*)d_in[4];
    const float* Rhw = (const float*)d_in[5],  *Rhb = (const float*)d_in[6];
    const float* Rew = (const float*)d_in[7],  *Reb = (const float*)d_in[8];
    const float* Psw = (const float*)d_in[9],  *Psb = (const float*)d_in[10];
    const float* Phw = (const float*)d_in[11], *Phb = (const float*)d_in[12];
    const float* Pew = (const float*)d_in[13], *Peb = (const float*)d_in[14];

    const int N = in_sizes[0];   // score is (N, 1)
    const int E = in_sizes[2];   // outcome is (E,)

    const int tb = 256, nb = (N + tb - 1) / tb;
    // edge_kernel stays at kernel-launch index 3 (the slot ncu captures).
    zero_kernel<<<nb, tb>>>(N);                                    // 0
    prep_kernel<<<1, 256>>>(Rsw, Rsb, Rhw, Rhb, Rew, Reb,
                            Psw, Psb, Phw, Phb, Pew, Peb);         // 1
    scal_kernel<<<1, 1>>>();                                       // 2

    // copy packed R-net image into constant memory (D2D, capturable)
    void* wp_addr = nullptr;
    cudaGetSymbolAddress(&wp_addr, g_wpack);
    cudaMemcpyToSymbolAsync(c_w, wp_addr, NET_STRIDE * sizeof(u64), 0,
                            cudaMemcpyDeviceToDevice, 0);

    edge_kernel<<<(E + 127) / 128, 128>>>(score, edge_idx, outcome, E);  // 3
    reduce1_kernel<<<nb, tb>>>(score, N);                          // 4
    reduce2_kernel<<<nb, tb>>>(score, N);                          // 5
    finalize_kernel<<<nb, tb>>>((float*)d_out, N);                 // 6
}

// round 10
// speedup vs baseline: 1.5555x; 1.5555x over previous
#include <cuda_runtime.h>
#include <cuda_bf16.h>

typedef unsigned long long u64;

#define NMAX 100000

// ---------------- device scratch ----------------
__device__ float g_agg[NMAX];
__device__ int   g_deg[NMAX];
__device__ float g_tmp[NMAX];
__device__ int   g_degmax;
__device__ float g_sum_agg;
__device__ float g_sum_score;
__device__ float g_sumsq;

// ---------------- packed weight image -----------------------------------
// u64 = {w[j][2i], w[j][2i+1]}. Bias folded into row slot 0 as {b,0},
// multiplied against a constant {1,1} input lane. Row bases even (16B).
// Per net (u64 units):
//   L0: 35 rows x 6  (slot0 bias, slots1-5 = 5 kpairs of K=10)      [0,210)
//   Hm: 35 rows x 20 (slot0 bias, 1..18 kpairs of K=35, 19 pad)     [210+700m)
//   E : 5 rows x 20                                                 [2310,2410)
#define OFF_L0 0
#define OFF_H0 210
#define OFF_H1 910
#define OFF_H2 1610
#define OFF_E  2310
#define NET_STRIDE 2410
#define WPACK_U64 (2 * NET_STRIDE)   // 4820 u64 = 38560 B

__device__ u64 g_wpack[WPACK_U64];

// ---------------- f32x2 helpers ----------------
__device__ __forceinline__ u64 fma2(u64 a, u64 b, u64 c) {
    u64 d;
    asm("fma.rn.f32x2 %0, %1, %2, %3;" : "=l"(d) : "l"(a), "l"(b), "l"(c));
    return d;
}
__device__ __forceinline__ u64 add2(u64 a, u64 b) {
    u64 d;
    asm("add.rn.f32x2 %0, %1, %2;" : "=l"(d) : "l"(a), "l"(b));
    return d;
}
__device__ __forceinline__ u64 pk(float lo, float hi) {
    return ((u64)__float_as_uint(hi) << 32) | (u64)__float_as_uint(lo);
}
__device__ __forceinline__ float lo32(u64 a) { return __uint_as_float((unsigned)a); }
__device__ __forceinline__ float hi32(u64 a) { return __uint_as_float((unsigned)(a >> 32)); }
__device__ __forceinline__ float sigmoidf(float v) { return 1.0f / (1.0f + __expf(-v)); }
__device__ __forceinline__ float hsum(u64 a0, u64 a1) {
    u64 s = add2(a0, a1);
    return lo32(s) + hi32(s);
}

// One weight row (NU2 ulonglong2 = 2*NU2 kpairs incl. bias slot) dotted with
// TWO edges' packed inputs. 4 fma2 per 16B load.
template<int NU2>
__device__ __forceinline__ void row2(const u64* __restrict__ wr,
                                     const u64* __restrict__ xA,
                                     const u64* __restrict__ xB,
                                     float& vA, float& vB) {
    u64 aA0 = 0ull, aA1 = 0ull, aB0 = 0ull, aB1 = 0ull;
#pragma unroll
    for (int i = 0; i < NU2; i++) {
        ulonglong2 w2 = reinterpret_cast<const ulonglong2*>(wr)[i];
        aA0 = fma2(w2.x, xA[2 * i],     aA0);
        aA1 = fma2(w2.y, xA[2 * i + 1], aA1);
        aB0 = fma2(w2.x, xB[2 * i],     aB0);
        aB1 = fma2(w2.y, xB[2 * i + 1], aB1);
    }
    vA = hsum(aA0, aA1);
    vB = hsum(aB0, aB1);
}

// Dense layer for two edges. Outputs packed into o*[1..], slot 0 stays {1,1}.
template<int NROW, int NU2, int STRIDE, bool RELU>
__device__ __forceinline__ void layer2(const u64* __restrict__ w,
                                       const u64* __restrict__ xA,
                                       const u64* __restrict__ xB,
                                       u64* __restrict__ oA,
                                       u64* __restrict__ oB) {
#pragma unroll 4
    for (int jp = 0; jp < NROW / 2; jp++) {
        float a0, b0, a1, b1;
        row2<NU2>(w + (2 * jp)     * STRIDE, xA, xB, a0, b0);
        row2<NU2>(w + (2 * jp + 1) * STRIDE, xA, xB, a1, b1);
        if (RELU) {
            a0 = fmaxf(a0, 0.0f); a1 = fmaxf(a1, 0.0f);
            b0 = fmaxf(b0, 0.0f); b1 = fmaxf(b1, 0.0f);
        }
        oA[1 + jp] = pk(a0, a1);
        oB[1 + jp] = pk(b0, b1);
    }
    if (NROW & 1) {
        float a, b;
        row2<NU2>(w + (NROW - 1) * STRIDE, xA, xB, a, b);
        if (RELU) { a = fmaxf(a, 0.0f); b = fmaxf(b, 0.0f); }
        oA[1 + NROW / 2] = pk(a, 0.0f);
        oB[1 + NROW / 2] = pk(b, 0.0f);
    }
}

// ---------------- small kernels ----------------
__global__ void zero_kernel(int N) {
    int i = blockIdx.x * blockDim.x + threadIdx.x;
    if (i < N) { g_agg[i] = 0.0f; g_deg[i] = 0; }
}
__global__ void scal_kernel() {
    g_degmax = 0; g_sum_agg = 0.0f; g_sum_score = 0.0f; g_sumsq = 0.0f;
}

// Build the packed weight image once.
__global__ void prep_kernel(
    const float* __restrict__ Rsw, const float* __restrict__ Rsb,
    const float* __restrict__ Rhw, const float* __restrict__ Rhb,
    const float* __restrict__ Rew, const float* __restrict__ Reb,
    const float* __restrict__ Psw, const float* __restrict__ Psb,
    const float* __restrict__ Phw, const float* __restrict__ Phb,
    const float* __restrict__ Pew, const float* __restrict__ Peb)
{
    const int t = threadIdx.x, nt = blockDim.x;
    float* wf = reinterpret_cast<float*>(g_wpack);
    for (int k = t; k < 2 * WPACK_U64; k += nt) wf[k] = 0.0f;
    __syncthreads();

    // matrix+bias into rows: slot0={b,0}, slot(1+i/2) lane(i&1) = w[j][i]
    auto put = [&](const float* __restrict__ w, const float* __restrict__ b,
                   int offU, int rows, int cols, int stride) {
        int n = rows * cols;
        for (int k = t; k < n; k += nt) {
            int j = k / cols, i = k - j * cols;
            wf[(offU + j * stride + 1 + (i >> 1)) * 2 + (i & 1)] = w[k];
        }
        for (int j = t; j < rows; j += nt)
            wf[(offU + j * stride) * 2] = b[j];
    };

    // R net
    put(Rsw, Rsb, OFF_L0, 35, 10, 6);
    for (int m = 0; m < 3; m++)
        put(Rhw + m * 1225, Rhb + m * 35, OFF_H0 + m * 700, 35, 35, 20);
    put(Rew, Reb, OFF_E, 5, 35, 20);   // only first 5 rows needed
    // P net
    put(Psw, Psb, NET_STRIDE + OFF_L0, 35, 10, 6);
    for (int m = 0; m < 3; m++)
        put(Phw + m * 1225, Phb + m * 35, NET_STRIDE + OFF_H0 + m * 700, 35, 35, 20);
    put(Pew, Peb, NET_STRIDE + OFF_E, 5, 35, 20);
}

// ---------------- edge kernel: 2 edges per thread ----------------
__global__ void __launch_bounds__(128) edge_kernel(
    const float* __restrict__ score,
    const int*   __restrict__ edge_idx,
    const float* __restrict__ outcome,
    int E)
{
    __shared__ __align__(16) u64 wsm[WPACK_U64];
    const int t = threadIdx.x, nt = blockDim.x;
    {
        const ulonglong2* src = reinterpret_cast<const ulonglong2*>(g_wpack);
        ulonglong2* dst = reinterpret_cast<ulonglong2*>(wsm);
        for (int k = t; k < WPACK_U64 / 2; k += nt) dst[k] = src[k];
    }
    __syncthreads();

    const int P = (E + 1) >> 1;
    const int p = blockIdx.x * blockDim.x + t;
    if (p >= P) return;

    const int eA = p;
    const int eB = (p + P < E) ? (p + P) : p;   // degenerate dup if E odd
    const bool wrB = (p + P < E);

    const bool oA = outcome[eA] > 0.0f;
    const bool oB = outcome[eB] > 0.0f;

#pragma unroll 1
    for (int net = 0; net < 2; net++) {   // 0 = R (+sig), 1 = P (-sig)
        const u64* W = wsm + net * NET_STRIDE;
        const bool fA = (net == 0) ? oA : !oA;
        const bool fB = (net == 0) ? oB : !oB;

        u64 pA[20], pB[20], qA[20], qB[20];
        pA[0] = pB[0] = qA[0] = qB[0] = pk(1.0f, 1.0f);
        pA[19] = pB[19] = qA[19] = qB[19] = 0ull;

        // gather + orient input pairs into p*[1..5]
        {
            const int2* ei = reinterpret_cast<const int2*>(edge_idx + (size_t)eA * 10);
            int2 q[5];
#pragma unroll
            for (int k = 0; k < 5; k++) q[k] = ei[k];
#pragma unroll
            for (int k = 0; k < 5; k++) {
                int2 a = fA ? q[k] : make_int2(q[4 - k].y, q[4 - k].x);
                pA[1 + k] = pk(score[a.x], score[a.y]);
            }
        }
        {
            const int2* ei = reinterpret_cast<const int2*>(edge_idx + (size_t)eB * 10);
            int2 q[5];
#pragma unroll
            for (int k = 0; k < 5; k++) q[k] = ei[k];
#pragma unroll
            for (int k = 0; k < 5; k++) {
                int2 a = fB ? q[k] : make_int2(q[4 - k].y, q[4 - k].x);
                pB[1 + k] = pk(score[a.x], score[a.y]);
            }
        }

        layer2<35,  3,  6, true>(W + OFF_L0, pA, pB, qA, qB);
        layer2<35, 10, 20, true>(W + OFF_H0, qA, qB, pA, pB);
        layer2<35, 10, 20, true>(W + OFF_H1, pA, pB, qA, qB);
        layer2<35, 10, 20, true>(W + OFF_H2, qA, qB, pA, pB);

        float yA[5], yB[5];
#pragma unroll
        for (int r = 0; r < 5; r++)
            row2<10>(W + OFF_E + r * 20, pA, pB, yA[r], yB[r]);

        const float sgn = (net == 0) ? 1.0f : -1.0f;
        // scatter edge A (reload needed indices; L1-hot)
        {
            const int base = (net == 0) ? (oA ? 0 : 5) : (oA ? 5 : 0);
            const int* ii = edge_idx + (size_t)eA * 10 + base;
#pragma unroll
            for (int j = 0; j < 5; j++)
                atomicAdd(&g_agg[ii[j]], sgn * sigmoidf(yA[j]));
        }
        if (wrB) {
            const int base = (net == 0) ? (oB ? 0 : 5) : (oB ? 5 : 0);
            const int* ii = edge_idx + (size_t)eB * 10 + base;
#pragma unroll
            for (int j = 0; j < 5; j++)
                atomicAdd(&g_agg[ii[j]], sgn * sigmoidf(yB[j]));
        }
    }

    // degree counts
    {
        const int* ii = edge_idx + (size_t)eA * 10;
#pragma unroll
        for (int k = 0; k < 10; k++) atomicAdd(&g_deg[ii[k]], 1);
        if (wrB) {
            const int* jj = edge_idx + (size_t)eB * 10;
#pragma unroll
            for (int k = 0; k < 10; k++) atomicAdd(&g_deg[jj[k]], 1);
        }
    }
}

__device__ __forceinline__ float warp_sum(float v) {
#pragma unroll
    for (int s = 16; s; s >>= 1) v += __shfl_xor_sync(0xffffffffu, v, s);
    return v;
}
__device__ __forceinline__ int warp_max(int v) {
#pragma unroll
    for (int s = 16; s; s >>= 1) v = max(v, __shfl_xor_sync(0xffffffffu, v, s));
    return v;
}

__global__ void reduce1_kernel(const float* __restrict__ score, int N) {
    int i = blockIdx.x * blockDim.x + threadIdx.x;
    int d = 0; float sa = 0.0f, ss = 0.0f;
    if (i < N) { d = g_deg[i]; sa = g_agg[i]; ss = score[i]; }
    sa = warp_sum(sa); ss = warp_sum(ss); d = warp_max(d);
    if ((threadIdx.x & 31) == 0) {
        atomicMax(&g_degmax, d);
        atomicAdd(&g_sum_agg, sa);
        atomicAdd(&g_sum_score, ss);
    }
}

__global__ void reduce2_kernel(const float* __restrict__ score, int N) {
    const float c    = 2.0f / (float)g_degmax;
    const float mean = (g_sum_score + c * g_sum_agg) / (float)N;
    int i = blockIdx.x * blockDim.x + threadIdx.x;
    float u = 0.0f;
    if (i < N) { u = score[i] + c * g_agg[i] - mean; g_tmp[i] = u; }
    float sq = warp_sum(u * u);
    if ((threadIdx.x & 31) == 0) atomicAdd(&g_sumsq, sq);
}

__global__ void finalize_kernel(float* __restrict__ out, int N) {
    int i = blockIdx.x * blockDim.x + threadIdx.x;
    if (i < N) out[i] = g_tmp[i] * rsqrtf(g_sumsq);
}

// ---------------- launch ----------------
extern "C" void kernel_launch(void* const* d_in, const int* in_sizes, int n_in,
                              void* d_out, int out_size) {
    const float* score    = (const float*)d_in[0];
    const int*   edge_idx = (const int*)  d_in[1];
    const float* outcome  = (const float*)d_in[2];
    const float* Rsw = (const float*)d_in[3],  *Rsb = (const float*)d_in[4];
    const float* Rhw = (const float*)d_in[5],  *Rhb = (const float*)d_in[6];
    const float* Rew = (const float*)d_in[7],  *Reb = (const float*)d_in[8];
    const float* Psw = (const float*)d_in[9],  *Psb = (const float*)d_in[10];
    const float* Phw = (const float*)d_in[11], *Phb = (const float*)d_in[12];
    const float* Pew = (const float*)d_in[13], *Peb = (const float*)d_in[14];

    const int N = in_sizes[0];
    const int E = in_sizes[2];

    const int tb = 256, nb = (N + tb - 1) / tb;
    // edge_kernel at launch index 3 (the slot ncu captures)
    zero_kernel<<<nb, tb>>>(N);                                    // 0
    prep_kernel<<<1, 256>>>(Rsw, Rsb, Rhw, Rhb, Rew, Reb,
                            Psw, Psb, Phw, Phb, Pew, Peb);         // 1
    scal_kernel<<<1, 1>>>();                                       // 2

    const int P = (E + 1) / 2;
    edge_kernel<<<(P + 127) / 128, 128>>>(score, edge_idx, outcome, E);  // 3
    reduce1_kernel<<<nb, tb>>>(score, N);                          // 4
    reduce2_kernel<<<nb, tb>>>(score, N);                          // 5
    finalize_kernel<<<nb, tb>>>((float*)d_out, N);                 // 6
}